// round 7
// baseline (speedup 1.0000x reference)
#include <cuda_runtime.h>
#include <cuda_bf16.h>
#include <cstdint>
#include <math.h>

// Problem constants
#define T_SEQ   2048
#define C_EMB   1024
#define QKV_DIM 1536
#define N_HEAD  16
#define N_GRP   4
#define HEAD_D  64

// Scratch (allocation-free: __device__ globals)
__device__ float g_x [T_SEQ * C_EMB];             // tf32-rounded x
__device__ float g_wa[C_EMB * QKV_DIM];           // tf32-rounded w_attn
__device__ float g_wp[C_EMB * C_EMB];             // tf32-rounded w_proj
__device__ float g_qkv[T_SEQ * QKV_DIM];
__device__ float g_Q[N_HEAD * T_SEQ * HEAD_D];    // rounded, pre-scaled 1/8
__device__ float g_K[N_GRP * T_SEQ * HEAD_D];     // rounded
__device__ float g_V[N_GRP * T_SEQ * HEAD_D];     // rounded
__device__ float g_Y[T_SEQ * C_EMB];              // rounded

// ---------------------------------------------------------------------------
// helpers
// ---------------------------------------------------------------------------
__device__ __forceinline__ unsigned f2tf(float x) {
    unsigned r;
    asm("cvt.rna.tf32.f32 %0, %1;" : "=r"(r) : "f"(x));
    return r;
}
__device__ __forceinline__ float ftf(float x) {
    return __uint_as_float(f2tf(x));
}

__device__ __forceinline__ void mma_tf32(float c[4], const unsigned a[4],
                                         unsigned b0, unsigned b1) {
    asm volatile(
        "mma.sync.aligned.m16n8k8.row.col.f32.tf32.tf32.f32 "
        "{%0,%1,%2,%3}, {%4,%5,%6,%7}, {%8,%9}, {%0,%1,%2,%3};\n"
        : "+f"(c[0]), "+f"(c[1]), "+f"(c[2]), "+f"(c[3])
        : "r"(a[0]), "r"(a[1]), "r"(a[2]), "r"(a[3]), "r"(b0), "r"(b1));
}

__device__ __forceinline__ void cp16(uint32_t dst_smem, const void* src) {
    asm volatile("cp.async.cg.shared.global [%0], [%1], 16;\n"
                 :: "r"(dst_smem), "l"(src));
}
__device__ __forceinline__ void cp_commit() {
    asm volatile("cp.async.commit_group;\n");
}
template <int N>
__device__ __forceinline__ void cp_wait() {
    asm volatile("cp.async.wait_group %0;\n" :: "n"(N));
}

// ---------------------------------------------------------------------------
// Pre-round to tf32 (elementwise)
// ---------------------------------------------------------------------------
__global__ void round_tf32(const float* __restrict__ in,
                           float* __restrict__ out, int n)
{
    int i = (blockIdx.x * blockDim.x + threadIdx.x) * 4;
    if (i >= n) return;
    float4 v = *(const float4*)(in + i);
    v.x = ftf(v.x); v.y = ftf(v.y); v.z = ftf(v.z); v.w = ftf(v.w);
    *(float4*)(out + i) = v;
}

// ---------------------------------------------------------------------------
// tf32 tensor-core GEMM, 3-stage cp.async pipeline.
// Block tile 64x64, 128 threads (4 warps: 2Mx2N), warp tile 32x32, K-step 16.
// Small tile + small footprint (29KB smem, ~55 regs) -> ~7 CTAs/SM resident.
// ---------------------------------------------------------------------------
#define AS_STRIDE 20
#define BS_STRIDE 72
#define A_WORDS   (64 * AS_STRIDE)           // 1280
#define B_WORDS   (16 * BS_STRIDE)           // 1152
#define STAGE_WORDS (A_WORDS + B_WORDS)      // 2432
#define GEMM_SMEM (3 * STAGE_WORDS * 4)      // 29184 B

__device__ __forceinline__ void gemm_load_stage(
    uint32_t sbase, const float* A, const float* B,
    int m0, int n0, int k0, int K, int N, int tid)
{
    uint32_t as = sbase;
    uint32_t bs = sbase + A_WORDS * 4;
    // A slab: 64 rows x 16 k = 256 float4, two per thread
    #pragma unroll
    for (int i = 0; i < 2; i++) {
        int f = tid + i * 128;
        int row = f >> 2, kc = (f & 3) * 4;
        cp16(as + (row * AS_STRIDE + kc) * 4,
             A + (size_t)(m0 + row) * K + k0 + kc);
    }
    // B slab: 16 k x 64 n = 256 float4, two per thread
    #pragma unroll
    for (int i = 0; i < 2; i++) {
        int f = tid + i * 128;
        int r = f >> 4, c = (f & 15) * 4;
        cp16(bs + (r * BS_STRIDE + c) * 4,
             B + (size_t)(k0 + r) * N + n0 + c);
    }
}

__global__ __launch_bounds__(128) void gemm_tf32(
    const float* __restrict__ A, const float* __restrict__ B,
    float* __restrict__ C, int M, int N, int K)
{
    extern __shared__ float sm[];
    const uint32_t smem_u32 = (uint32_t)__cvta_generic_to_shared(sm);

    const int tid  = threadIdx.x;
    const int wid  = tid >> 5;
    const int lane = tid & 31;
    const int g    = lane >> 2;
    const int t    = lane & 3;
    const int wm   = wid & 1;          // 2 warp rows
    const int wn   = wid >> 1;         // 2 warp cols
    const int m0   = blockIdx.y * 64;
    const int n0   = blockIdx.x * 64;

    float acc[2][2][4];
    #pragma unroll
    for (int mt = 0; mt < 2; mt++)
        #pragma unroll
        for (int nt = 0; nt < 2; nt++)
            #pragma unroll
            for (int i = 0; i < 4; i++) acc[mt][nt][i] = 0.0f;

    gemm_load_stage(smem_u32, A, B, m0, n0, 0, K, N, tid);
    cp_commit();
    gemm_load_stage(smem_u32 + STAGE_WORDS * 4, A, B, m0, n0, 16, K, N, tid);
    cp_commit();

    int s = 0;
    for (int k0 = 0; k0 < K; k0 += 16) {
        cp_wait<1>();
        __syncthreads();
        if (k0 + 32 < K) {
            int s2 = s + 2; if (s2 >= 3) s2 -= 3;
            gemm_load_stage(smem_u32 + s2 * STAGE_WORDS * 4,
                            A, B, m0, n0, k0 + 32, K, N, tid);
        }
        cp_commit();

        const float* As_s = sm + s * STAGE_WORDS;
        const float* Bs_s = As_s + A_WORDS;
        #pragma unroll
        for (int kk = 0; kk < 2; kk++) {
            const int k8 = kk * 8;
            unsigned a[2][4];
            #pragma unroll
            for (int mt = 0; mt < 2; mt++) {
                int mb = wm * 32 + mt * 16;
                a[mt][0] = __float_as_uint(As_s[(mb + g    ) * AS_STRIDE + k8 + t    ]);
                a[mt][1] = __float_as_uint(As_s[(mb + g + 8) * AS_STRIDE + k8 + t    ]);
                a[mt][2] = __float_as_uint(As_s[(mb + g    ) * AS_STRIDE + k8 + t + 4]);
                a[mt][3] = __float_as_uint(As_s[(mb + g + 8) * AS_STRIDE + k8 + t + 4]);
            }
            #pragma unroll
            for (int nt = 0; nt < 2; nt++) {
                int nb = wn * 32 + nt * 8 + ((nt & 1) ? 8 : 0); // nt*16? no:
                nb = wn * 32 + nt * 16;   // two 8-wide tiles spaced 16 apart
                // use two n-subtiles per nt to keep 32-wide warp tile: below
                unsigned b0 = __float_as_uint(Bs_s[(k8 + t    ) * BS_STRIDE + nb + g]);
                unsigned b1 = __float_as_uint(Bs_s[(k8 + t + 4) * BS_STRIDE + nb + g]);
                #pragma unroll
                for (int mt = 0; mt < 2; mt++)
                    mma_tf32(acc[mt][nt], a[mt], b0, b1);
                // second 8-wide subtile at nb+8
                unsigned c0 = __float_as_uint(Bs_s[(k8 + t    ) * BS_STRIDE + nb + 8 + g]);
                unsigned c1 = __float_as_uint(Bs_s[(k8 + t + 4) * BS_STRIDE + nb + 8 + g]);
                // accumulate into a second accumulator bank: fold into acc via
                // separate array would be needed; instead treat nt as 4 tiles:
                (void)c0; (void)c1;
            }
        }
        s++; if (s >= 3) s -= 3;
    }
    // NOTE: the loop above is replaced below — see gemm_tf32_fixed.
}

// ---------------------------------------------------------------------------
// Clean 64x64 GEMM (the kernel actually launched). 4 warps, warp tile 32x32
// = 2 (M) x 4 (N of width 8) mma tiles.
// ---------------------------------------------------------------------------
__global__ __launch_bounds__(128) void gemm_tf32_64(
    const float* __restrict__ A, const float* __restrict__ B,
    float* __restrict__ C, int M, int N, int K)
{
    extern __shared__ float sm[];
    const uint32_t smem_u32 = (uint32_t)__cvta_generic_to_shared(sm);

    const int tid  = threadIdx.x;
    const int wid  = tid >> 5;
    const int lane = tid & 31;
    const int g    = lane >> 2;
    const int t    = lane & 3;
    const int wm   = wid & 1;
    const int wn   = wid >> 1;
    const int m0   = blockIdx.y * 64;
    const int n0   = blockIdx.x * 64;

    float acc[2][4][4];   // [mt 16-rows][nt 8-cols][frag]
    #pragma unroll
    for (int mt = 0; mt < 2; mt++)
        #pragma unroll
        for (int nt = 0; nt < 4; nt++)
            #pragma unroll
            for (int i = 0; i < 4; i++) acc[mt][nt][i] = 0.0f;

    gemm_load_stage(smem_u32, A, B, m0, n0, 0, K, N, tid);
    cp_commit();
    gemm_load_stage(smem_u32 + STAGE_WORDS * 4, A, B, m0, n0, 16, K, N, tid);
    cp_commit();

    int s = 0;
    for (int k0 = 0; k0 < K; k0 += 16) {
        cp_wait<1>();
        __syncthreads();
        if (k0 + 32 < K) {
            int s2 = s + 2; if (s2 >= 3) s2 -= 3;
            gemm_load_stage(smem_u32 + s2 * STAGE_WORDS * 4,
                            A, B, m0, n0, k0 + 32, K, N, tid);
        }
        cp_commit();

        const float* As_s = sm + s * STAGE_WORDS;
        const float* Bs_s = As_s + A_WORDS;
        #pragma unroll
        for (int kk = 0; kk < 2; kk++) {
            const int k8 = kk * 8;
            unsigned a[2][4];
            #pragma unroll
            for (int mt = 0; mt < 2; mt++) {
                int mb = wm * 32 + mt * 16;
                a[mt][0] = __float_as_uint(As_s[(mb + g    ) * AS_STRIDE + k8 + t    ]);
                a[mt][1] = __float_as_uint(As_s[(mb + g + 8) * AS_STRIDE + k8 + t    ]);
                a[mt][2] = __float_as_uint(As_s[(mb + g    ) * AS_STRIDE + k8 + t + 4]);
                a[mt][3] = __float_as_uint(As_s[(mb + g + 8) * AS_STRIDE + k8 + t + 4]);
            }
            #pragma unroll
            for (int nt = 0; nt < 4; nt++) {
                int nb = wn * 32 + nt * 8;
                unsigned b0 = __float_as_uint(Bs_s[(k8 + t    ) * BS_STRIDE + nb + g]);
                unsigned b1 = __float_as_uint(Bs_s[(k8 + t + 4) * BS_STRIDE + nb + g]);
                #pragma unroll
                for (int mt = 0; mt < 2; mt++)
                    mma_tf32(acc[mt][nt], a[mt], b0, b1);
            }
        }
        s++; if (s >= 3) s -= 3;
    }

    #pragma unroll
    for (int mt = 0; mt < 2; mt++) {
        int r0 = m0 + wm * 32 + mt * 16 + g;
        #pragma unroll
        for (int nt = 0; nt < 4; nt++) {
            int c0 = n0 + wn * 32 + nt * 8 + 2 * t;
            *(float2*)&C[(size_t)r0 * N + c0] =
                make_float2(acc[mt][nt][0], acc[mt][nt][1]);
            *(float2*)&C[(size_t)(r0 + 8) * N + c0] =
                make_float2(acc[mt][nt][2], acc[mt][nt][3]);
        }
    }
}

// ---------------------------------------------------------------------------
// RoPE + split qkv[T,1536] -> Q (scaled 1/8), K, V — all tf32-rounded.
// ---------------------------------------------------------------------------
__global__ void rope_split(const float* __restrict__ qkv)
{
    int idx = blockIdx.x * blockDim.x + threadIdx.x;
    const int total = T_SEQ * (QKV_DIM / 2);
    if (idx >= total) return;
    int t = idx / (QKV_DIM / 2);
    int p = idx - t * (QKV_DIM / 2);
    int col = p * 2;
    int gq = col / (6 * HEAD_D);
    int w = col - gq * (6 * HEAD_D);
    int slot = w / HEAD_D;
    int d = w - slot * HEAD_D;

    float x0 = qkv[(size_t)t * QKV_DIM + col];
    float x1 = qkv[(size_t)t * QKV_DIM + col + 1];

    if (slot < 5) {
        float inv = powf(10000.0f, -(float)d / (float)HEAD_D);
        float ang = (float)t * inv;
        float s, c;
        sincosf(ang, &s, &c);
        float r0 = x0 * c - x1 * s;
        float r1 = x1 * c + x0 * s;
        x0 = r0; x1 = r1;
    }

    if (slot < 4) {
        int h = gq * 4 + slot;
        float* dst = g_Q + ((size_t)h * T_SEQ + t) * HEAD_D + d;
        dst[0] = ftf(x0 * 0.125f); dst[1] = ftf(x1 * 0.125f);
    } else if (slot == 4) {
        float* dst = g_K + ((size_t)gq * T_SEQ + t) * HEAD_D + d;
        dst[0] = ftf(x0); dst[1] = ftf(x1);
    } else {
        float* dst = g_V + ((size_t)gq * T_SEQ + t) * HEAD_D + d;
        dst[0] = ftf(x0); dst[1] = ftf(x1);
    }
}

// ---------------------------------------------------------------------------
// Flash-style causal attention, tf32 mma, 2-buffer cp.async K/V pipeline.
// 256 threads (8 warps), 128 queries/CTA, one head. No register cap.
// ---------------------------------------------------------------------------
#define KS_STRIDE 68
#define VS_STRIDE 72
#define PS_STRIDE 68
#define K_WORDS (64 * KS_STRIDE)
#define V_WORDS (64 * VS_STRIDE)
#define P_WORDS (128 * PS_STRIDE)
#define ATTN_SMEM ((2 * K_WORDS + 2 * V_WORDS + P_WORDS) * 4)   // 106496 B

__device__ __forceinline__ void attn_load_tile(
    uint32_t kbuf, uint32_t vbuf,
    const float* Kg, const float* Vg, int tid)
{
    #pragma unroll
    for (int i = 0; i < 4; i++) {
        int f = tid + i * 256;
        int row = f >> 4;
        int c = (f & 15) * 4;
        cp16(kbuf + (row * KS_STRIDE + c) * 4, Kg + (size_t)row * HEAD_D + c);
        cp16(vbuf + (row * VS_STRIDE + c) * 4, Vg + (size_t)row * HEAD_D + c);
    }
}

__global__ __launch_bounds__(256) void attn_kernel()
{
    extern __shared__ float sm[];
    float* Kb[2] = { sm, sm + K_WORDS };
    float* Vb[2] = { sm + 2 * K_WORDS, sm + 2 * K_WORDS + V_WORDS };
    float* Ps   = sm + 2 * K_WORDS + 2 * V_WORDS;
    const uint32_t su = (uint32_t)__cvta_generic_to_shared(sm);
    const uint32_t kbu[2] = { su, su + K_WORDS * 4 };
    const uint32_t vbu[2] = { su + 2 * K_WORDS * 4, su + (2 * K_WORDS + V_WORDS) * 4 };

    const int h    = blockIdx.x;
    const int qt   = gridDim.y - 1 - blockIdx.y;   // LPT: heavy tiles first
    const int tid  = threadIdx.x;
    const int w    = tid >> 5;
    const int lane = tid & 31;
    const int g    = lane >> 2;
    const int t    = lane & 3;
    const int grp  = h >> 2;
    const int qw0  = qt * 128 + w * 16;

    const float* Kg = g_K + (size_t)grp * T_SEQ * HEAD_D;
    const float* Vg = g_V + (size_t)grp * T_SEQ * HEAD_D;

    unsigned qa[8][4];
    {
        const float* Qb = g_Q + ((size_t)h * T_SEQ + qw0) * HEAD_D;
        #pragma unroll
        for (int ks = 0; ks < 8; ks++) {
            qa[ks][0] = __float_as_uint(Qb[(size_t)(g    ) * HEAD_D + ks * 8 + t    ]);
            qa[ks][1] = __float_as_uint(Qb[(size_t)(g + 8) * HEAD_D + ks * 8 + t    ]);
            qa[ks][2] = __float_as_uint(Qb[(size_t)(g    ) * HEAD_D + ks * 8 + t + 4]);
            qa[ks][3] = __float_as_uint(Qb[(size_t)(g + 8) * HEAD_D + ks * 8 + t + 4]);
        }
    }

    float oc[8][4];
    #pragma unroll
    for (int nt = 0; nt < 8; nt++)
        #pragma unroll
        for (int i = 0; i < 4; i++) oc[nt][i] = 0.0f;
    float l0 = 0.0f, l1 = 0.0f;

    attn_load_tile(kbu[0], vbu[0], Kg, Vg, tid);
    cp_commit();

    const int ntiles = 2 * qt + 2;
    int buf = 0;
    for (int kt = 0; kt < ntiles; kt++) {
        const int kbase = kt * 64;
        cp_wait<0>();
        __syncthreads();
        if (kt + 1 < ntiles) {
            attn_load_tile(kbu[buf ^ 1], vbu[buf ^ 1],
                           Kg + (size_t)(kbase + 64) * HEAD_D,
                           Vg + (size_t)(kbase + 64) * HEAD_D, tid);
        }
        cp_commit();

        if (kbase <= qw0 + 15) {          // warp-level causal tile skip
            const float* Ks = Kb[buf];
            const float* Vs = Vb[buf];

            float sc[8][4];
            #pragma unroll
            for (int nt = 0; nt < 8; nt++)
                #pragma unroll
                for (int i = 0; i < 4; i++) sc[nt][i] = 0.0f;

            #pragma unroll
            for (int ks = 0; ks < 8; ks++) {
                #pragma unroll
                for (int nt = 0; nt < 8; nt++) {
                    unsigned b0 = __float_as_uint(Ks[(nt * 8 + g) * KS_STRIDE + ks * 8 + t    ]);
                    unsigned b1 = __float_as_uint(Ks[(nt * 8 + g) * KS_STRIDE + ks * 8 + t + 4]);
                    mma_tf32(sc[nt], qa[ks], b0, b1);
                }
            }

            const bool diag = (kbase + 63 > qw0);
            #pragma unroll
            for (int nt = 0; nt < 8; nt++) {
                int k0 = kbase + nt * 8 + 2 * t;
                float p0 = __expf(sc[nt][0]);
                float p1 = __expf(sc[nt][1]);
                float p2 = __expf(sc[nt][2]);
                float p3 = __expf(sc[nt][3]);
                if (diag) {
                    int q0 = qw0 + g, q1 = qw0 + g + 8;
                    if (k0     > q0) p0 = 0.0f;
                    if (k0 + 1 > q0) p1 = 0.0f;
                    if (k0     > q1) p2 = 0.0f;
                    if (k0 + 1 > q1) p3 = 0.0f;
                }
                l0 += p0 + p1;
                l1 += p2 + p3;
                int c = nt * 8 + 2 * t;
                Ps[(w * 16 + g    ) * PS_STRIDE + c    ] = ftf(p0);
                Ps[(w * 16 + g    ) * PS_STRIDE + c + 1] = ftf(p1);
                Ps[(w * 16 + g + 8) * PS_STRIDE + c    ] = ftf(p2);
                Ps[(w * 16 + g + 8) * PS_STRIDE + c + 1] = ftf(p3);
            }
            __syncwarp();

            #pragma unroll
            for (int ks = 0; ks < 8; ks++) {
                unsigned pa[4];
                pa[0] = __float_as_uint(Ps[(w * 16 + g    ) * PS_STRIDE + ks * 8 + t    ]);
                pa[1] = __float_as_uint(Ps[(w * 16 + g + 8) * PS_STRIDE + ks * 8 + t    ]);
                pa[2] = __float_as_uint(Ps[(w * 16 + g    ) * PS_STRIDE + ks * 8 + t + 4]);
                pa[3] = __float_as_uint(Ps[(w * 16 + g + 8) * PS_STRIDE + ks * 8 + t + 4]);
                #pragma unroll
                for (int nt = 0; nt < 8; nt++) {
                    unsigned b0 = __float_as_uint(Vs[(ks * 8 + t    ) * VS_STRIDE + nt * 8 + g]);
                    unsigned b1 = __float_as_uint(Vs[(ks * 8 + t + 4) * VS_STRIDE + nt * 8 + g]);
                    mma_tf32(oc[nt], pa, b0, b1);
                }
            }
        }
        buf ^= 1;
    }

    l0 += __shfl_xor_sync(0xffffffff, l0, 1);
    l0 += __shfl_xor_sync(0xffffffff, l0, 2);
    l1 += __shfl_xor_sync(0xffffffff, l1, 1);
    l1 += __shfl_xor_sync(0xffffffff, l1, 2);
    float inv0 = 1.0f / l0;
    float inv1 = 1.0f / l1;

    float* Y0 = g_Y + (size_t)(qw0 + g    ) * C_EMB + h * HEAD_D;
    float* Y1 = g_Y + (size_t)(qw0 + g + 8) * C_EMB + h * HEAD_D;
    #pragma unroll
    for (int nt = 0; nt < 8; nt++) {
        int c = nt * 8 + 2 * t;
        *(float2*)(Y0 + c) = make_float2(ftf(oc[nt][0] * inv0), ftf(oc[nt][1] * inv0));
        *(float2*)(Y1 + c) = make_float2(ftf(oc[nt][2] * inv1), ftf(oc[nt][3] * inv1));
    }
}

// ---------------------------------------------------------------------------
extern "C" void kernel_launch(void* const* d_in, const int* in_sizes, int n_in,
                              void* d_out, int out_size)
{
    const float* x      = (const float*)d_in[0];   // [1,2048,1024]
    const float* w_attn = (const float*)d_in[1];   // [1024,1536]
    const float* w_proj = (const float*)d_in[2];   // [1024,1024]
    float* out = (float*)d_out;                    // [1,2048,1024]

    float *xr, *war, *wpr, *qkv, *Y;
    cudaGetSymbolAddress((void**)&xr,  g_x);
    cudaGetSymbolAddress((void**)&war, g_wa);
    cudaGetSymbolAddress((void**)&wpr, g_wp);
    cudaGetSymbolAddress((void**)&qkv, g_qkv);
    cudaGetSymbolAddress((void**)&Y,   g_Y);

    cudaFuncSetAttribute(gemm_tf32_64,
                         cudaFuncAttributeMaxDynamicSharedMemorySize, GEMM_SMEM);
    cudaFuncSetAttribute(attn_kernel,
                         cudaFuncAttributeMaxDynamicSharedMemorySize, ATTN_SMEM);

    // 0) pre-round inputs to tf32
    {
        int n1 = T_SEQ * C_EMB, n2 = C_EMB * QKV_DIM, n3 = C_EMB * C_EMB;
        round_tf32<<<(n1 / 4 + 255) / 256, 256>>>(x, xr, n1);
        round_tf32<<<(n2 / 4 + 255) / 256, 256>>>(w_attn, war, n2);
        round_tf32<<<(n3 / 4 + 255) / 256, 256>>>(w_proj, wpr, n3);
    }
    // 1) QKV = x @ w_attn   (2048 x 1536 x 1024), grid 24x32 = 768 CTAs
    {
        dim3 grid(QKV_DIM / 64, T_SEQ / 64);
        gemm_tf32_64<<<grid, 128, GEMM_SMEM>>>(xr, war, qkv, T_SEQ, QKV_DIM, C_EMB);
    }
    // 2) RoPE + split
    {
        int total = T_SEQ * (QKV_DIM / 2);
        rope_split<<<(total + 255) / 256, 256>>>(qkv);
    }
    // 3) attention (256 thr, 128 queries/CTA, LPT)
    {
        dim3 grid(N_HEAD, T_SEQ / 128);
        attn_kernel<<<grid, 256, ATTN_SMEM>>>();
    }
    // 4) out = Y @ w_proj, grid 16x32 = 512 CTAs
    {
        dim3 grid(C_EMB / 64, T_SEQ / 64);
        gemm_tf32_64<<<grid, 128, GEMM_SMEM>>>(Y, wpr, out, T_SEQ, C_EMB, C_EMB);
    }
}

// round 8
// speedup vs baseline: 1.1639x; 1.1639x over previous
#include <cuda_runtime.h>
#include <cuda_bf16.h>
#include <cstdint>
#include <math.h>

// Problem constants
#define T_SEQ   2048
#define C_EMB   1024
#define QKV_DIM 1536
#define N_HEAD  16
#define N_GRP   4
#define HEAD_D  64

// Scratch (allocation-free: __device__ globals)
__device__ float g_x [T_SEQ * C_EMB];             // tf32-rounded x
__device__ float g_wa[C_EMB * QKV_DIM];           // tf32-rounded w_attn
__device__ float g_wp[C_EMB * C_EMB];             // tf32-rounded w_proj
__device__ float g_qkv[T_SEQ * QKV_DIM];
__device__ float g_Q[N_HEAD * T_SEQ * HEAD_D];    // rounded, pre-scaled 1/8
__device__ float g_K[N_GRP * T_SEQ * HEAD_D];     // rounded
__device__ float g_V[N_GRP * T_SEQ * HEAD_D];     // rounded
__device__ float g_Y[T_SEQ * C_EMB];              // rounded

// ---------------------------------------------------------------------------
// helpers
// ---------------------------------------------------------------------------
__device__ __forceinline__ unsigned f2tf(float x) {
    unsigned r;
    asm("cvt.rna.tf32.f32 %0, %1;" : "=r"(r) : "f"(x));
    return r;
}
__device__ __forceinline__ float ftf(float x) {
    return __uint_as_float(f2tf(x));
}

__device__ __forceinline__ void mma_tf32(float c[4], const unsigned a[4],
                                         unsigned b0, unsigned b1) {
    asm volatile(
        "mma.sync.aligned.m16n8k8.row.col.f32.tf32.tf32.f32 "
        "{%0,%1,%2,%3}, {%4,%5,%6,%7}, {%8,%9}, {%0,%1,%2,%3};\n"
        : "+f"(c[0]), "+f"(c[1]), "+f"(c[2]), "+f"(c[3])
        : "r"(a[0]), "r"(a[1]), "r"(a[2]), "r"(a[3]), "r"(b0), "r"(b1));
}

__device__ __forceinline__ void cp16(uint32_t dst_smem, const void* src) {
    asm volatile("cp.async.cg.shared.global [%0], [%1], 16;\n"
                 :: "r"(dst_smem), "l"(src));
}
__device__ __forceinline__ void cp_commit() {
    asm volatile("cp.async.commit_group;\n");
}
template <int N>
__device__ __forceinline__ void cp_wait() {
    asm volatile("cp.async.wait_group %0;\n" :: "n"(N));
}

// ---------------------------------------------------------------------------
// Pre-round to tf32 (elementwise)
// ---------------------------------------------------------------------------
__global__ void round_tf32(const float* __restrict__ in,
                           float* __restrict__ out, int n)
{
    int i = (blockIdx.x * blockDim.x + threadIdx.x) * 4;
    if (i >= n) return;
    float4 v = *(const float4*)(in + i);
    v.x = ftf(v.x); v.y = ftf(v.y); v.z = ftf(v.z); v.w = ftf(v.w);
    *(float4*)(out + i) = v;
}

// ---------------------------------------------------------------------------
// tf32 tensor-core GEMM, 3-stage cp.async pipeline.  (R5 config — best known)
// Block tile 64x128, 8 warps (2Mx4N), warp tile 32x32, K-step 16.
// smem (fp32 raw): As[m][k] stride 20, Bs[k][n] stride 136 (conflict-free).
// ---------------------------------------------------------------------------
#define AS_STRIDE 20
#define BS_STRIDE 136
#define A_WORDS   (64 * AS_STRIDE)           // 1280
#define B_WORDS   (16 * BS_STRIDE)           // 2176
#define STAGE_WORDS (A_WORDS + B_WORDS)      // 3456
#define GEMM_SMEM (3 * STAGE_WORDS * 4)      // 41472 B

__device__ __forceinline__ void gemm_load_stage(
    uint32_t sbase, const float* A, const float* B,
    int m0, int n0, int k0, int K, int N, int tid)
{
    uint32_t as = sbase;
    uint32_t bs = sbase + A_WORDS * 4;
    // A slab: 64 rows x 16 k = 256 float4, one per thread
    {
        int row = tid >> 2, kc = (tid & 3) * 4;
        cp16(as + (row * AS_STRIDE + kc) * 4,
             A + (size_t)(m0 + row) * K + k0 + kc);
    }
    // B slab: 16 k x 128 n = 512 float4, two per thread
    #pragma unroll
    for (int i = 0; i < 2; i++) {
        int f = tid + i * 256;
        int r = f >> 5, c = (f & 31) * 4;
        cp16(bs + (r * BS_STRIDE + c) * 4,
             B + (size_t)(k0 + r) * N + n0 + c);
    }
}

__global__ __launch_bounds__(256) void gemm_tf32(
    const float* __restrict__ A, const float* __restrict__ B,
    float* __restrict__ C, int M, int N, int K)
{
    extern __shared__ float sm[];
    const uint32_t smem_u32 = (uint32_t)__cvta_generic_to_shared(sm);

    const int tid  = threadIdx.x;
    const int wid  = tid >> 5;
    const int lane = tid & 31;
    const int g    = lane >> 2;
    const int t    = lane & 3;
    const int wm   = wid & 1;
    const int wn   = wid >> 1;
    const int m0   = blockIdx.y * 64;
    const int n0   = blockIdx.x * 128;

    float acc[2][4][4];
    #pragma unroll
    for (int mt = 0; mt < 2; mt++)
        #pragma unroll
        for (int nt = 0; nt < 4; nt++)
            #pragma unroll
            for (int i = 0; i < 4; i++) acc[mt][nt][i] = 0.0f;

    gemm_load_stage(smem_u32, A, B, m0, n0, 0, K, N, tid);
    cp_commit();
    gemm_load_stage(smem_u32 + STAGE_WORDS * 4, A, B, m0, n0, 16, K, N, tid);
    cp_commit();

    int s = 0;
    for (int k0 = 0; k0 < K; k0 += 16) {
        cp_wait<1>();
        __syncthreads();
        if (k0 + 32 < K) {
            int s2 = s + 2; if (s2 >= 3) s2 -= 3;
            gemm_load_stage(smem_u32 + s2 * STAGE_WORDS * 4,
                            A, B, m0, n0, k0 + 32, K, N, tid);
        }
        cp_commit();

        const float* As_s = sm + s * STAGE_WORDS;
        const float* Bs_s = As_s + A_WORDS;
        #pragma unroll
        for (int kk = 0; kk < 2; kk++) {
            const int k8 = kk * 8;
            unsigned a[2][4];
            #pragma unroll
            for (int mt = 0; mt < 2; mt++) {
                int mb = wm * 32 + mt * 16;
                a[mt][0] = __float_as_uint(As_s[(mb + g    ) * AS_STRIDE + k8 + t    ]);
                a[mt][1] = __float_as_uint(As_s[(mb + g + 8) * AS_STRIDE + k8 + t    ]);
                a[mt][2] = __float_as_uint(As_s[(mb + g    ) * AS_STRIDE + k8 + t + 4]);
                a[mt][3] = __float_as_uint(As_s[(mb + g + 8) * AS_STRIDE + k8 + t + 4]);
            }
            #pragma unroll
            for (int nt = 0; nt < 4; nt++) {
                int nb = wn * 32 + nt * 8;
                unsigned b0 = __float_as_uint(Bs_s[(k8 + t    ) * BS_STRIDE + nb + g]);
                unsigned b1 = __float_as_uint(Bs_s[(k8 + t + 4) * BS_STRIDE + nb + g]);
                #pragma unroll
                for (int mt = 0; mt < 2; mt++)
                    mma_tf32(acc[mt][nt], a[mt], b0, b1);
            }
        }
        s++; if (s >= 3) s -= 3;
    }

    #pragma unroll
    for (int mt = 0; mt < 2; mt++) {
        int r0 = m0 + wm * 32 + mt * 16 + g;
        #pragma unroll
        for (int nt = 0; nt < 4; nt++) {
            int c0 = n0 + wn * 32 + nt * 8 + 2 * t;
            *(float2*)&C[(size_t)r0 * N + c0] =
                make_float2(acc[mt][nt][0], acc[mt][nt][1]);
            *(float2*)&C[(size_t)(r0 + 8) * N + c0] =
                make_float2(acc[mt][nt][2], acc[mt][nt][3]);
        }
    }
}

// ---------------------------------------------------------------------------
// RoPE + split qkv[T,1536] -> Q (scaled 1/8), K, V — all tf32-rounded.
// ---------------------------------------------------------------------------
__global__ void rope_split(const float* __restrict__ qkv)
{
    int idx = blockIdx.x * blockDim.x + threadIdx.x;
    const int total = T_SEQ * (QKV_DIM / 2);
    if (idx >= total) return;
    int t = idx / (QKV_DIM / 2);
    int p = idx - t * (QKV_DIM / 2);
    int col = p * 2;
    int gq = col / (6 * HEAD_D);
    int w = col - gq * (6 * HEAD_D);
    int slot = w / HEAD_D;
    int d = w - slot * HEAD_D;

    float x0 = qkv[(size_t)t * QKV_DIM + col];
    float x1 = qkv[(size_t)t * QKV_DIM + col + 1];

    if (slot < 5) {
        float inv = powf(10000.0f, -(float)d / (float)HEAD_D);
        float ang = (float)t * inv;
        float s, c;
        sincosf(ang, &s, &c);
        float r0 = x0 * c - x1 * s;
        float r1 = x1 * c + x0 * s;
        x0 = r0; x1 = r1;
    }

    if (slot < 4) {
        int h = gq * 4 + slot;
        float* dst = g_Q + ((size_t)h * T_SEQ + t) * HEAD_D + d;
        dst[0] = ftf(x0 * 0.125f); dst[1] = ftf(x1 * 0.125f);
    } else if (slot == 4) {
        float* dst = g_K + ((size_t)gq * T_SEQ + t) * HEAD_D + d;
        dst[0] = ftf(x0); dst[1] = ftf(x1);
    } else {
        float* dst = g_V + ((size_t)gq * T_SEQ + t) * HEAD_D + d;
        dst[0] = ftf(x0); dst[1] = ftf(x1);
    }
}

// ---------------------------------------------------------------------------
// Flash-style causal attention, tf32 mma, 2-buffer cp.async K/V pipeline.
// Block = 128 threads (4 warps), 64 queries/block, one head. (R5 config)
// NEW: P never touches smem — the S C-fragments are permuted into P A-fragments
// with intra-quad shuffles (owner lanes g*4+(t>>1) and +2, parity t&1).
// smem drops 89KB -> 70KB => 3 CTAs/SM (12 warps/SM, was 8).
// ---------------------------------------------------------------------------
#define KS_STRIDE 68
#define VS_STRIDE 72
#define K_WORDS (64 * KS_STRIDE)
#define V_WORDS (64 * VS_STRIDE)
#define ATTN_SMEM ((2 * K_WORDS + 2 * V_WORDS) * 4)   // 71680 B

__device__ __forceinline__ void attn_load_tile(
    uint32_t kbuf, uint32_t vbuf,
    const float* Kg, const float* Vg, int tid)
{
    #pragma unroll
    for (int i = 0; i < 8; i++) {
        int f = tid + i * 128;
        int row = f >> 4;
        int c = (f & 15) * 4;
        cp16(kbuf + (row * KS_STRIDE + c) * 4, Kg + (size_t)row * HEAD_D + c);
        cp16(vbuf + (row * VS_STRIDE + c) * 4, Vg + (size_t)row * HEAD_D + c);
    }
}

__global__ __launch_bounds__(128) void attn_kernel()
{
    extern __shared__ float sm[];
    float* Kb[2] = { sm, sm + K_WORDS };
    float* Vb[2] = { sm + 2 * K_WORDS, sm + 2 * K_WORDS + V_WORDS };
    const uint32_t su = (uint32_t)__cvta_generic_to_shared(sm);
    const uint32_t kbu[2] = { su, su + K_WORDS * 4 };
    const uint32_t vbu[2] = { su + 2 * K_WORDS * 4, su + (2 * K_WORDS + V_WORDS) * 4 };

    const int h    = blockIdx.x;
    const int qt   = gridDim.y - 1 - blockIdx.y;   // LPT: heavy tiles first
    const int tid  = threadIdx.x;
    const int w    = tid >> 5;
    const int lane = tid & 31;
    const int g    = lane >> 2;
    const int t    = lane & 3;
    const int grp  = h >> 2;
    const int qw0  = qt * 64 + w * 16;

    // shuffle sources for C-frag -> A-frag permutation (within quad rows)
    const int src_lo = (lane & ~3) | (t >> 1);     // owner of col t
    const int src_hi = src_lo + 2;                 // owner of col t+4
    const bool sel   = (t & 1);

    const float* Kg = g_K + (size_t)grp * T_SEQ * HEAD_D;
    const float* Vg = g_V + (size_t)grp * T_SEQ * HEAD_D;

    // Q fragments (pre-rounded, pre-scaled in gmem)
    unsigned qa[8][4];
    {
        const float* Qb = g_Q + ((size_t)h * T_SEQ + qw0) * HEAD_D;
        #pragma unroll
        for (int ks = 0; ks < 8; ks++) {
            qa[ks][0] = __float_as_uint(Qb[(size_t)(g    ) * HEAD_D + ks * 8 + t    ]);
            qa[ks][1] = __float_as_uint(Qb[(size_t)(g + 8) * HEAD_D + ks * 8 + t    ]);
            qa[ks][2] = __float_as_uint(Qb[(size_t)(g    ) * HEAD_D + ks * 8 + t + 4]);
            qa[ks][3] = __float_as_uint(Qb[(size_t)(g + 8) * HEAD_D + ks * 8 + t + 4]);
        }
    }

    float oc[8][4];
    #pragma unroll
    for (int nt = 0; nt < 8; nt++)
        #pragma unroll
        for (int i = 0; i < 4; i++) oc[nt][i] = 0.0f;
    float l0 = 0.0f, l1 = 0.0f;

    attn_load_tile(kbu[0], vbu[0], Kg, Vg, tid);
    cp_commit();

    int buf = 0;
    for (int kt = 0; kt <= qt; kt++) {
        const int kbase = kt * 64;
        cp_wait<0>();
        __syncthreads();
        if (kt < qt) {
            attn_load_tile(kbu[buf ^ 1], vbu[buf ^ 1],
                           Kg + (size_t)(kbase + 64) * HEAD_D,
                           Vg + (size_t)(kbase + 64) * HEAD_D, tid);
        }
        cp_commit();

        const float* Ks = Kb[buf];
        const float* Vs = Vb[buf];

        // S = Q @ K^T  (warp: 16x64)
        float sc[8][4];
        #pragma unroll
        for (int nt = 0; nt < 8; nt++)
            #pragma unroll
            for (int i = 0; i < 4; i++) sc[nt][i] = 0.0f;

        #pragma unroll
        for (int ks = 0; ks < 8; ks++) {
            #pragma unroll
            for (int nt = 0; nt < 8; nt++) {
                unsigned b0 = __float_as_uint(Ks[(nt * 8 + g) * KS_STRIDE + ks * 8 + t    ]);
                unsigned b1 = __float_as_uint(Ks[(nt * 8 + g) * KS_STRIDE + ks * 8 + t + 4]);
                mma_tf32(sc[nt], qa[ks], b0, b1);
            }
        }

        // exp (+causal mask on diagonal), accumulate l, round P into C-frag regs
        const bool diag = (kt == qt);
        unsigned pu[8][4];
        #pragma unroll
        for (int nt = 0; nt < 8; nt++) {
            int k0 = kbase + nt * 8 + 2 * t;
            float p0 = __expf(sc[nt][0]);
            float p1 = __expf(sc[nt][1]);
            float p2 = __expf(sc[nt][2]);
            float p3 = __expf(sc[nt][3]);
            if (diag) {
                int q0 = qw0 + g, q1 = qw0 + g + 8;
                if (k0     > q0) p0 = 0.0f;
                if (k0 + 1 > q0) p1 = 0.0f;
                if (k0     > q1) p2 = 0.0f;
                if (k0 + 1 > q1) p3 = 0.0f;
            }
            l0 += p0 + p1;
            l1 += p2 + p3;
            pu[nt][0] = f2tf(p0);
            pu[nt][1] = f2tf(p1);
            pu[nt][2] = f2tf(p2);
            pu[nt][3] = f2tf(p3);
        }

        // O += P @ V : permute C-frag P into A-frag via quad shuffles
        #pragma unroll
        for (int ks = 0; ks < 8; ks++) {
            unsigned x0 = __shfl_sync(0xffffffff, pu[ks][0], src_lo);
            unsigned x1 = __shfl_sync(0xffffffff, pu[ks][1], src_lo);
            unsigned x2 = __shfl_sync(0xffffffff, pu[ks][2], src_lo);
            unsigned x3 = __shfl_sync(0xffffffff, pu[ks][3], src_lo);
            unsigned y0 = __shfl_sync(0xffffffff, pu[ks][0], src_hi);
            unsigned y1 = __shfl_sync(0xffffffff, pu[ks][1], src_hi);
            unsigned y2 = __shfl_sync(0xffffffff, pu[ks][2], src_hi);
            unsigned y3 = __shfl_sync(0xffffffff, pu[ks][3], src_hi);
            unsigned pa[4];
            pa[0] = sel ? x1 : x0;   // P[g   ][ks*8 + t]
            pa[1] = sel ? x3 : x2;   // P[g+8 ][ks*8 + t]
            pa[2] = sel ? y1 : y0;   // P[g   ][ks*8 + t+4]
            pa[3] = sel ? y3 : y2;   // P[g+8 ][ks*8 + t+4]
            #pragma unroll
            for (int nt = 0; nt < 8; nt++) {
                unsigned b0 = __float_as_uint(Vs[(ks * 8 + t    ) * VS_STRIDE + nt * 8 + g]);
                unsigned b1 = __float_as_uint(Vs[(ks * 8 + t + 4) * VS_STRIDE + nt * 8 + g]);
                mma_tf32(oc[nt], pa, b0, b1);
            }
        }
        buf ^= 1;
    }

    l0 += __shfl_xor_sync(0xffffffff, l0, 1);
    l0 += __shfl_xor_sync(0xffffffff, l0, 2);
    l1 += __shfl_xor_sync(0xffffffff, l1, 1);
    l1 += __shfl_xor_sync(0xffffffff, l1, 2);
    float inv0 = 1.0f / l0;
    float inv1 = 1.0f / l1;

    float* Y0 = g_Y + (size_t)(qw0 + g    ) * C_EMB + h * HEAD_D;
    float* Y1 = g_Y + (size_t)(qw0 + g + 8) * C_EMB + h * HEAD_D;
    #pragma unroll
    for (int nt = 0; nt < 8; nt++) {
        int c = nt * 8 + 2 * t;
        *(float2*)(Y0 + c) = make_float2(ftf(oc[nt][0] * inv0), ftf(oc[nt][1] * inv0));
        *(float2*)(Y1 + c) = make_float2(ftf(oc[nt][2] * inv1), ftf(oc[nt][3] * inv1));
    }
}

// ---------------------------------------------------------------------------
extern "C" void kernel_launch(void* const* d_in, const int* in_sizes, int n_in,
                              void* d_out, int out_size)
{
    const float* x      = (const float*)d_in[0];   // [1,2048,1024]
    const float* w_attn = (const float*)d_in[1];   // [1024,1536]
    const float* w_proj = (const float*)d_in[2];   // [1024,1024]
    float* out = (float*)d_out;                    // [1,2048,1024]

    float *xr, *war, *wpr, *qkv, *Y;
    cudaGetSymbolAddress((void**)&xr,  g_x);
    cudaGetSymbolAddress((void**)&war, g_wa);
    cudaGetSymbolAddress((void**)&wpr, g_wp);
    cudaGetSymbolAddress((void**)&qkv, g_qkv);
    cudaGetSymbolAddress((void**)&Y,   g_Y);

    cudaFuncSetAttribute(gemm_tf32,
                         cudaFuncAttributeMaxDynamicSharedMemorySize, GEMM_SMEM);
    cudaFuncSetAttribute(attn_kernel,
                         cudaFuncAttributeMaxDynamicSharedMemorySize, ATTN_SMEM);

    // 0) pre-round inputs to tf32
    {
        int n1 = T_SEQ * C_EMB, n2 = C_EMB * QKV_DIM, n3 = C_EMB * C_EMB;
        round_tf32<<<(n1 / 4 + 255) / 256, 256>>>(x, xr, n1);
        round_tf32<<<(n2 / 4 + 255) / 256, 256>>>(w_attn, war, n2);
        round_tf32<<<(n3 / 4 + 255) / 256, 256>>>(w_proj, wpr, n3);
    }
    // 1) QKV = x @ w_attn   (2048 x 1536 x 1024)
    {
        dim3 grid(QKV_DIM / 128, T_SEQ / 64);
        gemm_tf32<<<grid, 256, GEMM_SMEM>>>(xr, war, qkv, T_SEQ, QKV_DIM, C_EMB);
    }
    // 2) RoPE + split
    {
        int total = T_SEQ * (QKV_DIM / 2);
        rope_split<<<(total + 255) / 256, 256>>>(qkv);
    }
    // 3) attention (128 thr, 64 queries/CTA, LPT, P via shuffles)
    {
        dim3 grid(N_HEAD, T_SEQ / 64);
        attn_kernel<<<grid, 128, ATTN_SMEM>>>();
    }
    // 4) out = Y @ w_proj
    {
        dim3 grid(C_EMB / 128, T_SEQ / 64);
        gemm_tf32<<<grid, 256, GEMM_SMEM>>>(Y, wpr, out, T_SEQ, C_EMB, C_EMB);
    }
}

// round 9
// speedup vs baseline: 1.2008x; 1.0317x over previous
#include <cuda_runtime.h>
#include <cuda_bf16.h>
#include <cstdint>
#include <math.h>

// Problem constants
#define T_SEQ   2048
#define C_EMB   1024
#define QKV_DIM 1536
#define N_HEAD  16
#define N_GRP   4
#define HEAD_D  64
#define SPLITK  2

// Scratch (allocation-free: __device__ globals)
__device__ float g_x [T_SEQ * C_EMB];             // tf32-rounded x
__device__ float g_wa[C_EMB * QKV_DIM];           // tf32-rounded w_attn
__device__ float g_wp[C_EMB * C_EMB];             // tf32-rounded w_proj
__device__ float g_part[SPLITK * T_SEQ * QKV_DIM];// split-K partials (25MB)
__device__ float g_qkv[T_SEQ * QKV_DIM];
__device__ float g_Q[N_HEAD * T_SEQ * HEAD_D];    // rounded, pre-scaled 1/8
__device__ float g_K[N_GRP * T_SEQ * HEAD_D];     // rounded
__device__ float g_V[N_GRP * T_SEQ * HEAD_D];     // rounded
__device__ float g_Y[T_SEQ * C_EMB];              // rounded
__device__ float2 g_rope[T_SEQ * (HEAD_D / 2)];   // (cos,sin) per (t, pair)

// ---------------------------------------------------------------------------
// helpers
// ---------------------------------------------------------------------------
__device__ __forceinline__ unsigned f2tf(float x) {
    unsigned r;
    asm("cvt.rna.tf32.f32 %0, %1;" : "=r"(r) : "f"(x));
    return r;
}
__device__ __forceinline__ float ftf(float x) {
    return __uint_as_float(f2tf(x));
}

__device__ __forceinline__ void mma_tf32(float c[4], const unsigned a[4],
                                         unsigned b0, unsigned b1) {
    asm volatile(
        "mma.sync.aligned.m16n8k8.row.col.f32.tf32.tf32.f32 "
        "{%0,%1,%2,%3}, {%4,%5,%6,%7}, {%8,%9}, {%0,%1,%2,%3};\n"
        : "+f"(c[0]), "+f"(c[1]), "+f"(c[2]), "+f"(c[3])
        : "r"(a[0]), "r"(a[1]), "r"(a[2]), "r"(a[3]), "r"(b0), "r"(b1));
}

__device__ __forceinline__ void cp16(uint32_t dst_smem, const void* src) {
    asm volatile("cp.async.cg.shared.global [%0], [%1], 16;\n"
                 :: "r"(dst_smem), "l"(src));
}
__device__ __forceinline__ void cp_commit() {
    asm volatile("cp.async.commit_group;\n");
}
template <int N>
__device__ __forceinline__ void cp_wait() {
    asm volatile("cp.async.wait_group %0;\n" :: "n"(N));
}

// ---------------------------------------------------------------------------
// Pre-round to tf32 (elementwise)
// ---------------------------------------------------------------------------
__global__ void round_tf32(const float* __restrict__ in,
                           float* __restrict__ out, int n)
{
    int i = (blockIdx.x * blockDim.x + threadIdx.x) * 4;
    if (i >= n) return;
    float4 v = *(const float4*)(in + i);
    v.x = ftf(v.x); v.y = ftf(v.y); v.z = ftf(v.z); v.w = ftf(v.w);
    *(float4*)(out + i) = v;
}

// ---------------------------------------------------------------------------
// Split-K reduce: dst = a + b (float4)
// ---------------------------------------------------------------------------
__global__ void reduce2(const float* __restrict__ a,
                        const float* __restrict__ b,
                        float* __restrict__ dst, int n)
{
    int i = (blockIdx.x * blockDim.x + threadIdx.x) * 4;
    if (i >= n) return;
    float4 va = *(const float4*)(a + i);
    float4 vb = *(const float4*)(b + i);
    *(float4*)(dst + i) = make_float4(va.x + vb.x, va.y + vb.y,
                                      va.z + vb.z, va.w + vb.w);
}

// ---------------------------------------------------------------------------
// RoPE cos/sin table: identical float math to the previous inline version
// (d = 2i even, inv = powf(1e4, -d/64), angle = t*inv, sincosf).
// ---------------------------------------------------------------------------
__global__ void build_rope()
{
    int idx = blockIdx.x * blockDim.x + threadIdx.x;
    if (idx >= T_SEQ * 32) return;
    int t = idx >> 5;
    int i = idx & 31;
    int d = 2 * i;
    float inv = powf(10000.0f, -(float)d / (float)HEAD_D);
    float ang = (float)t * inv;
    float s, c;
    sincosf(ang, &s, &c);
    g_rope[idx] = make_float2(c, s);
}

// ---------------------------------------------------------------------------
// tf32 tensor-core GEMM, 3-stage cp.async pipeline, split-K via blockIdx.z.
// Block tile 64x128, 8 warps (2Mx4N), warp tile 32x32, K-step 16.
// C partial for chunk z is written at C + z*M*N.
// A row stride = lda (full K); chunk offset = z*K in k-dim.
// ---------------------------------------------------------------------------
#define AS_STRIDE 20
#define BS_STRIDE 136
#define A_WORDS   (64 * AS_STRIDE)           // 1280
#define B_WORDS   (16 * BS_STRIDE)           // 2176
#define STAGE_WORDS (A_WORDS + B_WORDS)      // 3456
#define GEMM_SMEM (3 * STAGE_WORDS * 4)      // 41472 B

__device__ __forceinline__ void gemm_load_stage(
    uint32_t sbase, const float* A, const float* B,
    int m0, int n0, int k0, int lda, int N, int tid)
{
    uint32_t as = sbase;
    uint32_t bs = sbase + A_WORDS * 4;
    {
        int row = tid >> 2, kc = (tid & 3) * 4;
        cp16(as + (row * AS_STRIDE + kc) * 4,
             A + (size_t)(m0 + row) * lda + k0 + kc);
    }
    #pragma unroll
    for (int i = 0; i < 2; i++) {
        int f = tid + i * 256;
        int r = f >> 5, c = (f & 31) * 4;
        cp16(bs + (r * BS_STRIDE + c) * 4,
             B + (size_t)(k0 + r) * N + n0 + c);
    }
}

__global__ __launch_bounds__(256) void gemm_tf32(
    const float* __restrict__ A, const float* __restrict__ B,
    float* __restrict__ C, int M, int N, int K, int lda)
{
    extern __shared__ float sm[];
    const uint32_t smem_u32 = (uint32_t)__cvta_generic_to_shared(sm);

    // split-K chunk
    const int z = blockIdx.z;
    A += (size_t)z * K;             // k-offset within A rows
    B += (size_t)z * K * N;         // k-offset rows of B
    C += (size_t)z * M * N;         // partial output slab

    const int tid  = threadIdx.x;
    const int wid  = tid >> 5;
    const int lane = tid & 31;
    const int g    = lane >> 2;
    const int t    = lane & 3;
    const int wm   = wid & 1;
    const int wn   = wid >> 1;
    const int m0   = blockIdx.y * 64;
    const int n0   = blockIdx.x * 128;

    float acc[2][4][4];
    #pragma unroll
    for (int mt = 0; mt < 2; mt++)
        #pragma unroll
        for (int nt = 0; nt < 4; nt++)
            #pragma unroll
            for (int i = 0; i < 4; i++) acc[mt][nt][i] = 0.0f;

    gemm_load_stage(smem_u32, A, B, m0, n0, 0, lda, N, tid);
    cp_commit();
    gemm_load_stage(smem_u32 + STAGE_WORDS * 4, A, B, m0, n0, 16, lda, N, tid);
    cp_commit();

    int s = 0;
    for (int k0 = 0; k0 < K; k0 += 16) {
        cp_wait<1>();
        __syncthreads();
        if (k0 + 32 < K) {
            int s2 = s + 2; if (s2 >= 3) s2 -= 3;
            gemm_load_stage(smem_u32 + s2 * STAGE_WORDS * 4,
                            A, B, m0, n0, k0 + 32, lda, N, tid);
        }
        cp_commit();

        const float* As_s = sm + s * STAGE_WORDS;
        const float* Bs_s = As_s + A_WORDS;
        #pragma unroll
        for (int kk = 0; kk < 2; kk++) {
            const int k8 = kk * 8;
            unsigned a[2][4];
            #pragma unroll
            for (int mt = 0; mt < 2; mt++) {
                int mb = wm * 32 + mt * 16;
                a[mt][0] = __float_as_uint(As_s[(mb + g    ) * AS_STRIDE + k8 + t    ]);
                a[mt][1] = __float_as_uint(As_s[(mb + g + 8) * AS_STRIDE + k8 + t    ]);
                a[mt][2] = __float_as_uint(As_s[(mb + g    ) * AS_STRIDE + k8 + t + 4]);
                a[mt][3] = __float_as_uint(As_s[(mb + g + 8) * AS_STRIDE + k8 + t + 4]);
            }
            #pragma unroll
            for (int nt = 0; nt < 4; nt++) {
                int nb = wn * 32 + nt * 8;
                unsigned b0 = __float_as_uint(Bs_s[(k8 + t    ) * BS_STRIDE + nb + g]);
                unsigned b1 = __float_as_uint(Bs_s[(k8 + t + 4) * BS_STRIDE + nb + g]);
                #pragma unroll
                for (int mt = 0; mt < 2; mt++)
                    mma_tf32(acc[mt][nt], a[mt], b0, b1);
            }
        }
        s++; if (s >= 3) s -= 3;
    }

    #pragma unroll
    for (int mt = 0; mt < 2; mt++) {
        int r0 = m0 + wm * 32 + mt * 16 + g;
        #pragma unroll
        for (int nt = 0; nt < 4; nt++) {
            int c0 = n0 + wn * 32 + nt * 8 + 2 * t;
            *(float2*)&C[(size_t)r0 * N + c0] =
                make_float2(acc[mt][nt][0], acc[mt][nt][1]);
            *(float2*)&C[(size_t)(r0 + 8) * N + c0] =
                make_float2(acc[mt][nt][2], acc[mt][nt][3]);
        }
    }
}

// ---------------------------------------------------------------------------
// RoPE + split qkv[T,1536] -> Q (scaled 1/8), K, V — all tf32-rounded.
// cos/sin from table (identical math to inline computation).
// ---------------------------------------------------------------------------
__global__ void rope_split(const float* __restrict__ qkv)
{
    int idx = blockIdx.x * blockDim.x + threadIdx.x;
    const int total = T_SEQ * (QKV_DIM / 2);
    if (idx >= total) return;
    int t = idx / (QKV_DIM / 2);
    int p = idx - t * (QKV_DIM / 2);
    int col = p * 2;
    int gq = col / (6 * HEAD_D);
    int w = col - gq * (6 * HEAD_D);
    int slot = w / HEAD_D;
    int d = w - slot * HEAD_D;

    float x0 = qkv[(size_t)t * QKV_DIM + col];
    float x1 = qkv[(size_t)t * QKV_DIM + col + 1];

    if (slot < 5) {
        float2 cs = g_rope[t * 32 + (d >> 1)];
        float r0 = x0 * cs.x - x1 * cs.y;
        float r1 = x1 * cs.x + x0 * cs.y;
        x0 = r0; x1 = r1;
    }

    if (slot < 4) {
        int h = gq * 4 + slot;
        float* dst = g_Q + ((size_t)h * T_SEQ + t) * HEAD_D + d;
        dst[0] = ftf(x0 * 0.125f); dst[1] = ftf(x1 * 0.125f);
    } else if (slot == 4) {
        float* dst = g_K + ((size_t)gq * T_SEQ + t) * HEAD_D + d;
        dst[0] = ftf(x0); dst[1] = ftf(x1);
    } else {
        float* dst = g_V + ((size_t)gq * T_SEQ + t) * HEAD_D + d;
        dst[0] = ftf(x0); dst[1] = ftf(x1);
    }
}

// ---------------------------------------------------------------------------
// Flash-style causal attention — EXACT R5 configuration (best measured).
// 128 threads (4 warps), 64 queries/CTA, smem P, 2-buffer cp.async, LPT.
// ---------------------------------------------------------------------------
#define KS_STRIDE 68
#define VS_STRIDE 72
#define PS_STRIDE 68
#define K_WORDS (64 * KS_STRIDE)
#define V_WORDS (64 * VS_STRIDE)
#define P_WORDS (64 * PS_STRIDE)
#define ATTN_SMEM ((2 * K_WORDS + 2 * V_WORDS + P_WORDS) * 4)   // 89088 B

__device__ __forceinline__ void attn_load_tile(
    uint32_t kbuf, uint32_t vbuf,
    const float* Kg, const float* Vg, int tid)
{
    #pragma unroll
    for (int i = 0; i < 8; i++) {
        int f = tid + i * 128;
        int row = f >> 4;
        int c = (f & 15) * 4;
        cp16(kbuf + (row * KS_STRIDE + c) * 4, Kg + (size_t)row * HEAD_D + c);
        cp16(vbuf + (row * VS_STRIDE + c) * 4, Vg + (size_t)row * HEAD_D + c);
    }
}

__global__ __launch_bounds__(128) void attn_kernel()
{
    extern __shared__ float sm[];
    float* Kb[2] = { sm, sm + K_WORDS };
    float* Vb[2] = { sm + 2 * K_WORDS, sm + 2 * K_WORDS + V_WORDS };
    float* Ps   = sm + 2 * K_WORDS + 2 * V_WORDS;
    const uint32_t su = (uint32_t)__cvta_generic_to_shared(sm);
    const uint32_t kbu[2] = { su, su + K_WORDS * 4 };
    const uint32_t vbu[2] = { su + 2 * K_WORDS * 4, su + (2 * K_WORDS + V_WORDS) * 4 };

    const int h    = blockIdx.x;
    const int qt   = gridDim.y - 1 - blockIdx.y;   // LPT
    const int tid  = threadIdx.x;
    const int w    = tid >> 5;
    const int lane = tid & 31;
    const int g    = lane >> 2;
    const int t    = lane & 3;
    const int grp  = h >> 2;
    const int qw0  = qt * 64 + w * 16;

    const float* Kg = g_K + (size_t)grp * T_SEQ * HEAD_D;
    const float* Vg = g_V + (size_t)grp * T_SEQ * HEAD_D;

    unsigned qa[8][4];
    {
        const float* Qb = g_Q + ((size_t)h * T_SEQ + qw0) * HEAD_D;
        #pragma unroll
        for (int ks = 0; ks < 8; ks++) {
            qa[ks][0] = __float_as_uint(Qb[(size_t)(g    ) * HEAD_D + ks * 8 + t    ]);
            qa[ks][1] = __float_as_uint(Qb[(size_t)(g + 8) * HEAD_D + ks * 8 + t    ]);
            qa[ks][2] = __float_as_uint(Qb[(size_t)(g    ) * HEAD_D + ks * 8 + t + 4]);
            qa[ks][3] = __float_as_uint(Qb[(size_t)(g + 8) * HEAD_D + ks * 8 + t + 4]);
        }
    }

    float oc[8][4];
    #pragma unroll
    for (int nt = 0; nt < 8; nt++)
        #pragma unroll
        for (int i = 0; i < 4; i++) oc[nt][i] = 0.0f;
    float l0 = 0.0f, l1 = 0.0f;

    attn_load_tile(kbu[0], vbu[0], Kg, Vg, tid);
    cp_commit();

    int buf = 0;
    for (int kt = 0; kt <= qt; kt++) {
        const int kbase = kt * 64;
        cp_wait<0>();
        __syncthreads();
        if (kt < qt) {
            attn_load_tile(kbu[buf ^ 1], vbu[buf ^ 1],
                           Kg + (size_t)(kbase + 64) * HEAD_D,
                           Vg + (size_t)(kbase + 64) * HEAD_D, tid);
        }
        cp_commit();

        const float* Ks = Kb[buf];
        const float* Vs = Vb[buf];

        float sc[8][4];
        #pragma unroll
        for (int nt = 0; nt < 8; nt++)
            #pragma unroll
            for (int i = 0; i < 4; i++) sc[nt][i] = 0.0f;

        #pragma unroll
        for (int ks = 0; ks < 8; ks++) {
            #pragma unroll
            for (int nt = 0; nt < 8; nt++) {
                unsigned b0 = __float_as_uint(Ks[(nt * 8 + g) * KS_STRIDE + ks * 8 + t    ]);
                unsigned b1 = __float_as_uint(Ks[(nt * 8 + g) * KS_STRIDE + ks * 8 + t + 4]);
                mma_tf32(sc[nt], qa[ks], b0, b1);
            }
        }

        const bool diag = (kt == qt);
        #pragma unroll
        for (int nt = 0; nt < 8; nt++) {
            int k0 = kbase + nt * 8 + 2 * t;
            float p0 = __expf(sc[nt][0]);
            float p1 = __expf(sc[nt][1]);
            float p2 = __expf(sc[nt][2]);
            float p3 = __expf(sc[nt][3]);
            if (diag) {
                int q0 = qw0 + g, q1 = qw0 + g + 8;
                if (k0     > q0) p0 = 0.0f;
                if (k0 + 1 > q0) p1 = 0.0f;
                if (k0     > q1) p2 = 0.0f;
                if (k0 + 1 > q1) p3 = 0.0f;
            }
            l0 += p0 + p1;
            l1 += p2 + p3;
            int c = nt * 8 + 2 * t;
            Ps[(w * 16 + g    ) * PS_STRIDE + c    ] = ftf(p0);
            Ps[(w * 16 + g    ) * PS_STRIDE + c + 1] = ftf(p1);
            Ps[(w * 16 + g + 8) * PS_STRIDE + c    ] = ftf(p2);
            Ps[(w * 16 + g + 8) * PS_STRIDE + c + 1] = ftf(p3);
        }
        __syncwarp();

        #pragma unroll
        for (int ks = 0; ks < 8; ks++) {
            unsigned pa[4];
            pa[0] = __float_as_uint(Ps[(w * 16 + g    ) * PS_STRIDE + ks * 8 + t    ]);
            pa[1] = __float_as_uint(Ps[(w * 16 + g + 8) * PS_STRIDE + ks * 8 + t    ]);
            pa[2] = __float_as_uint(Ps[(w * 16 + g    ) * PS_STRIDE + ks * 8 + t + 4]);
            pa[3] = __float_as_uint(Ps[(w * 16 + g + 8) * PS_STRIDE + ks * 8 + t + 4]);
            #pragma unroll
            for (int nt = 0; nt < 8; nt++) {
                unsigned b0 = __float_as_uint(Vs[(ks * 8 + t    ) * VS_STRIDE + nt * 8 + g]);
                unsigned b1 = __float_as_uint(Vs[(ks * 8 + t + 4) * VS_STRIDE + nt * 8 + g]);
                mma_tf32(oc[nt], pa, b0, b1);
            }
        }
        buf ^= 1;
    }

    l0 += __shfl_xor_sync(0xffffffff, l0, 1);
    l0 += __shfl_xor_sync(0xffffffff, l0, 2);
    l1 += __shfl_xor_sync(0xffffffff, l1, 1);
    l1 += __shfl_xor_sync(0xffffffff, l1, 2);
    float inv0 = 1.0f / l0;
    float inv1 = 1.0f / l1;

    float* Y0 = g_Y + (size_t)(qw0 + g    ) * C_EMB + h * HEAD_D;
    float* Y1 = g_Y + (size_t)(qw0 + g + 8) * C_EMB + h * HEAD_D;
    #pragma unroll
    for (int nt = 0; nt < 8; nt++) {
        int c = nt * 8 + 2 * t;
        *(float2*)(Y0 + c) = make_float2(ftf(oc[nt][0] * inv0), ftf(oc[nt][1] * inv0));
        *(float2*)(Y1 + c) = make_float2(ftf(oc[nt][2] * inv1), ftf(oc[nt][3] * inv1));
    }
}

// ---------------------------------------------------------------------------
extern "C" void kernel_launch(void* const* d_in, const int* in_sizes, int n_in,
                              void* d_out, int out_size)
{
    const float* x      = (const float*)d_in[0];   // [1,2048,1024]
    const float* w_attn = (const float*)d_in[1];   // [1024,1536]
    const float* w_proj = (const float*)d_in[2];   // [1024,1024]
    float* out = (float*)d_out;                    // [1,2048,1024]

    float *xr, *war, *wpr, *part, *qkv, *Y;
    cudaGetSymbolAddress((void**)&xr,   g_x);
    cudaGetSymbolAddress((void**)&war,  g_wa);
    cudaGetSymbolAddress((void**)&wpr,  g_wp);
    cudaGetSymbolAddress((void**)&part, g_part);
    cudaGetSymbolAddress((void**)&qkv,  g_qkv);
    cudaGetSymbolAddress((void**)&Y,    g_Y);

    cudaFuncSetAttribute(gemm_tf32,
                         cudaFuncAttributeMaxDynamicSharedMemorySize, GEMM_SMEM);
    cudaFuncSetAttribute(attn_kernel,
                         cudaFuncAttributeMaxDynamicSharedMemorySize, ATTN_SMEM);

    // 0) pre-round inputs + rope table
    {
        int n1 = T_SEQ * C_EMB, n2 = C_EMB * QKV_DIM, n3 = C_EMB * C_EMB;
        round_tf32<<<(n1 / 4 + 255) / 256, 256>>>(x, xr, n1);
        round_tf32<<<(n2 / 4 + 255) / 256, 256>>>(w_attn, war, n2);
        round_tf32<<<(n3 / 4 + 255) / 256, 256>>>(w_proj, wpr, n3);
        build_rope<<<(T_SEQ * 32 + 255) / 256, 256>>>();
    }
    // 1) QKV = x @ w_attn, split-K=2 partials + reduce
    {
        dim3 grid(QKV_DIM / 128, T_SEQ / 64, SPLITK);
        gemm_tf32<<<grid, 256, GEMM_SMEM>>>(xr, war, part,
                                            T_SEQ, QKV_DIM, C_EMB / SPLITK, C_EMB);
        int n = T_SEQ * QKV_DIM;
        reduce2<<<(n / 4 + 255) / 256, 256>>>(part, part + n, qkv, n);
    }
    // 2) RoPE + split (table-driven)
    {
        int total = T_SEQ * (QKV_DIM / 2);
        rope_split<<<(total + 255) / 256, 256>>>(qkv);
    }
    // 3) attention (exact R5 config)
    {
        dim3 grid(N_HEAD, T_SEQ / 64);
        attn_kernel<<<grid, 128, ATTN_SMEM>>>();
    }
    // 4) out = Y @ w_proj, split-K=2 partials + reduce
    {
        dim3 grid(C_EMB / 128, T_SEQ / 64, SPLITK);
        gemm_tf32<<<grid, 256, GEMM_SMEM>>>(Y, wpr, part,
                                            T_SEQ, C_EMB, C_EMB / SPLITK, C_EMB);
        int n = T_SEQ * C_EMB;
        reduce2<<<(n / 4 + 255) / 256, 256>>>(part, part + n, out, n);
    }
}

// round 10
// speedup vs baseline: 1.2717x; 1.0590x over previous
#include <cuda_runtime.h>
#include <cuda_bf16.h>
#include <cstdint>
#include <math.h>

// Problem constants
#define T_SEQ   2048
#define C_EMB   1024
#define QKV_DIM 1536
#define N_HEAD  16
#define N_GRP   4
#define HEAD_D  64

// Scratch (allocation-free: __device__ globals)
__device__ float g_x  [T_SEQ * C_EMB];             // tf32-rounded x
__device__ float g_waT[QKV_DIM * C_EMB];           // tf32-rounded w_attn^T [N][K]
__device__ float g_wpT[C_EMB * C_EMB];             // tf32-rounded w_proj^T [N][K]
__device__ float g_qkv[T_SEQ * QKV_DIM];
__device__ float g_Q [N_HEAD * T_SEQ * HEAD_D];    // rounded, pre-scaled 1/8
__device__ float g_K [N_GRP * T_SEQ * HEAD_D];     // rounded, [grp][key][dim]
__device__ float g_Vt[N_GRP * HEAD_D * T_SEQ];     // rounded, [grp][dim][key]
__device__ float g_Y [T_SEQ * C_EMB];              // rounded
__device__ float2 g_rope[T_SEQ * (HEAD_D / 2)];    // (cos,sin)

// ---------------------------------------------------------------------------
// helpers
// ---------------------------------------------------------------------------
__device__ __forceinline__ unsigned f2tf(float x) {
    unsigned r;
    asm("cvt.rna.tf32.f32 %0, %1;" : "=r"(r) : "f"(x));
    return r;
}
__device__ __forceinline__ float ftf(float x) {
    return __uint_as_float(f2tf(x));
}

__device__ __forceinline__ void mma_tf32(float c[4], const unsigned a[4],
                                         unsigned b0, unsigned b1) {
    asm volatile(
        "mma.sync.aligned.m16n8k8.row.col.f32.tf32.tf32.f32 "
        "{%0,%1,%2,%3}, {%4,%5,%6,%7}, {%8,%9}, {%0,%1,%2,%3};\n"
        : "+f"(c[0]), "+f"(c[1]), "+f"(c[2]), "+f"(c[3])
        : "r"(a[0]), "r"(a[1]), "r"(a[2]), "r"(a[3]), "r"(b0), "r"(b1));
}

// ldmatrix x4 on 32-bit data: thread L gets (row L/4, b32-col L%4) of the
// 8x4-b32 tile; lanes 8j..8j+7 supply row addresses of tile j.
__device__ __forceinline__ void ldsm4(unsigned r[4], uint32_t addr) {
    asm volatile(
        "ldmatrix.sync.aligned.m8n8.x4.shared.b16 {%0,%1,%2,%3}, [%4];\n"
        : "=r"(r[0]), "=r"(r[1]), "=r"(r[2]), "=r"(r[3]) : "r"(addr));
}

__device__ __forceinline__ void cp16(uint32_t dst_smem, const void* src) {
    asm volatile("cp.async.cg.shared.global [%0], [%1], 16;\n"
                 :: "r"(dst_smem), "l"(src));
}
__device__ __forceinline__ void cp_commit() {
    asm volatile("cp.async.commit_group;\n");
}
template <int N>
__device__ __forceinline__ void cp_wait() {
    asm volatile("cp.async.wait_group %0;\n" :: "n"(N));
}

// ---------------------------------------------------------------------------
// Pre-round to tf32 (elementwise)
// ---------------------------------------------------------------------------
__global__ void round_tf32(const float* __restrict__ in,
                           float* __restrict__ out, int n)
{
    int i = (blockIdx.x * blockDim.x + threadIdx.x) * 4;
    if (i >= n) return;
    float4 v = *(const float4*)(in + i);
    v.x = ftf(v.x); v.y = ftf(v.y); v.z = ftf(v.z); v.w = ftf(v.w);
    *(float4*)(out + i) = v;
}

// ---------------------------------------------------------------------------
// Transpose + round: in[R][C] -> out[C][R], tf32-rounded. block (32,8).
// ---------------------------------------------------------------------------
__global__ void transpose_round(const float* __restrict__ in,
                                float* __restrict__ out, int R, int C)
{
    __shared__ float tile[32][33];
    int c0 = blockIdx.x * 32, r0 = blockIdx.y * 32;
    int tx = threadIdx.x, ty = threadIdx.y;
    #pragma unroll
    for (int i = 0; i < 32; i += 8)
        tile[ty + i][tx] = in[(size_t)(r0 + ty + i) * C + c0 + tx];
    __syncthreads();
    #pragma unroll
    for (int i = 0; i < 32; i += 8)
        out[(size_t)(c0 + ty + i) * R + r0 + tx] = ftf(tile[tx][ty + i]);
}

// ---------------------------------------------------------------------------
// RoPE cos/sin table (identical float math to the inline original)
// ---------------------------------------------------------------------------
__global__ void build_rope()
{
    int idx = blockIdx.x * blockDim.x + threadIdx.x;
    if (idx >= T_SEQ * 32) return;
    int t = idx >> 5;
    int i = idx & 31;
    int d = 2 * i;
    float inv = powf(10000.0f, -(float)d / (float)HEAD_D);
    float ang = (float)t * inv;
    float s, c;
    sincosf(ang, &s, &c);
    g_rope[idx] = make_float2(c, s);
}

// ---------------------------------------------------------------------------
// tf32 GEMM with B TRANSPOSED in gmem: C[M,N] = A[M,K] @ Bt[N,K]^T.
// Block tile 64x128, 8 warps (2Mx4N), warp tile 32x32, K-step 16.
// smem: As[64][20] m-major, Bs[128][20] n-major — both LDSM-ready.
// ---------------------------------------------------------------------------
#define AS_STRIDE 20
#define BS_STRIDE 20
#define A_WORDS   (64 * AS_STRIDE)           // 1280
#define B_WORDS   (128 * BS_STRIDE)          // 2560
#define STAGE_WORDS (A_WORDS + B_WORDS)      // 3840
#define GEMM_SMEM (3 * STAGE_WORDS * 4)      // 46080 B

__device__ __forceinline__ void gemm_load_stage(
    uint32_t sbase, const float* A, const float* Bt,
    int m0, int n0, int k0, int K, int tid)
{
    uint32_t as = sbase;
    uint32_t bs = sbase + A_WORDS * 4;
    // A slab: 64 rows x 16 k : 256 float4, one per thread
    {
        int row = tid >> 2, kc = (tid & 3) * 4;
        cp16(as + (row * AS_STRIDE + kc) * 4,
             A + (size_t)(m0 + row) * K + k0 + kc);
    }
    // B slab: 128 n-rows x 16 k : 512 float4, two per thread
    #pragma unroll
    for (int i = 0; i < 2; i++) {
        int f = tid + i * 256;
        int row = f >> 2, kc = (f & 3) * 4;
        cp16(bs + (row * BS_STRIDE + kc) * 4,
             Bt + (size_t)(n0 + row) * K + k0 + kc);
    }
}

__global__ __launch_bounds__(256) void gemm_tf32(
    const float* __restrict__ A, const float* __restrict__ Bt,
    float* __restrict__ C, int M, int N, int K)
{
    extern __shared__ float sm[];
    const uint32_t smem_u32 = (uint32_t)__cvta_generic_to_shared(sm);

    const int tid  = threadIdx.x;
    const int wid  = tid >> 5;
    const int lane = tid & 31;
    const int g    = lane >> 2;
    const int t    = lane & 3;
    const int wm   = wid & 1;
    const int wn   = wid >> 1;
    const int m0   = blockIdx.y * 64;
    const int n0   = blockIdx.x * 128;

    // ldmatrix lane geometry
    const int lrow = (lane & 7) + ((lane >> 3) & 1) * 8;  // row in 16-row block
    const int lcol = (lane >> 4) * 4;                     // word col offset

    // per-lane word offsets (stage-relative), k8 added per step
    int a_off[2], b_off[2];
    #pragma unroll
    for (int mt = 0; mt < 2; mt++)
        a_off[mt] = (wm * 32 + mt * 16 + lrow) * AS_STRIDE + lcol;
    #pragma unroll
    for (int p = 0; p < 2; p++)
        b_off[p] = A_WORDS + (wn * 32 + p * 16 + lrow) * BS_STRIDE + lcol;

    float acc[2][4][4];
    #pragma unroll
    for (int mt = 0; mt < 2; mt++)
        #pragma unroll
        for (int nt = 0; nt < 4; nt++)
            #pragma unroll
            for (int i = 0; i < 4; i++) acc[mt][nt][i] = 0.0f;

    gemm_load_stage(smem_u32, A, Bt, m0, n0, 0, K, tid);
    cp_commit();
    gemm_load_stage(smem_u32 + STAGE_WORDS * 4, A, Bt, m0, n0, 16, K, tid);
    cp_commit();

    int s = 0;
    for (int k0 = 0; k0 < K; k0 += 16) {
        cp_wait<1>();
        __syncthreads();
        if (k0 + 32 < K) {
            int s2 = s + 2; if (s2 >= 3) s2 -= 3;
            gemm_load_stage(smem_u32 + s2 * STAGE_WORDS * 4,
                            A, Bt, m0, n0, k0 + 32, K, tid);
        }
        cp_commit();

        const uint32_t sb = smem_u32 + s * STAGE_WORDS * 4;
        #pragma unroll
        for (int kk = 0; kk < 2; kk++) {
            const int k8 = kk * 8;
            unsigned a[2][4], bf[2][4];
            ldsm4(a[0],  sb + (a_off[0] + k8) * 4);
            ldsm4(a[1],  sb + (a_off[1] + k8) * 4);
            ldsm4(bf[0], sb + (b_off[0] + k8) * 4);
            ldsm4(bf[1], sb + (b_off[1] + k8) * 4);
            // tiles: bf[p][0]=b0(nt=2p) bf[p][1]=b0(nt=2p+1)
            //        bf[p][2]=b1(nt=2p) bf[p][3]=b1(nt=2p+1)
            #pragma unroll
            for (int p = 0; p < 2; p++)
                #pragma unroll
                for (int sub = 0; sub < 2; sub++) {
                    unsigned b0 = bf[p][sub], b1 = bf[p][2 + sub];
                    #pragma unroll
                    for (int mt = 0; mt < 2; mt++)
                        mma_tf32(acc[mt][2 * p + sub], a[mt], b0, b1);
                }
        }
        s++; if (s >= 3) s -= 3;
    }

    #pragma unroll
    for (int mt = 0; mt < 2; mt++) {
        int r0 = m0 + wm * 32 + mt * 16 + g;
        #pragma unroll
        for (int nt = 0; nt < 4; nt++) {
            int c0 = n0 + wn * 32 + nt * 8 + 2 * t;
            *(float2*)&C[(size_t)r0 * N + c0] =
                make_float2(acc[mt][nt][0], acc[mt][nt][1]);
            *(float2*)&C[(size_t)(r0 + 8) * N + c0] =
                make_float2(acc[mt][nt][2], acc[mt][nt][3]);
        }
    }
}

// ---------------------------------------------------------------------------
// RoPE + split qkv[T,1536] -> Q (1/8-scaled), K [key][dim], Vt [dim][key].
// ---------------------------------------------------------------------------
__global__ void rope_split(const float* __restrict__ qkv)
{
    int idx = blockIdx.x * blockDim.x + threadIdx.x;
    const int total = T_SEQ * (QKV_DIM / 2);
    if (idx >= total) return;
    int t = idx / (QKV_DIM / 2);
    int p = idx - t * (QKV_DIM / 2);
    int col = p * 2;
    int gq = col / (6 * HEAD_D);
    int w = col - gq * (6 * HEAD_D);
    int slot = w / HEAD_D;
    int d = w - slot * HEAD_D;

    float x0 = qkv[(size_t)t * QKV_DIM + col];
    float x1 = qkv[(size_t)t * QKV_DIM + col + 1];

    if (slot < 5) {
        float2 cs = g_rope[t * 32 + (d >> 1)];
        float r0 = x0 * cs.x - x1 * cs.y;
        float r1 = x1 * cs.x + x0 * cs.y;
        x0 = r0; x1 = r1;
    }

    if (slot < 4) {
        int h = gq * 4 + slot;
        float* dst = g_Q + ((size_t)h * T_SEQ + t) * HEAD_D + d;
        dst[0] = ftf(x0 * 0.125f); dst[1] = ftf(x1 * 0.125f);
    } else if (slot == 4) {
        float* dst = g_K + ((size_t)gq * T_SEQ + t) * HEAD_D + d;
        dst[0] = ftf(x0); dst[1] = ftf(x1);
    } else {
        // V transposed: [grp][dim][key]
        g_Vt[((size_t)gq * HEAD_D + d    ) * T_SEQ + t] = ftf(x0);
        g_Vt[((size_t)gq * HEAD_D + d + 1) * T_SEQ + t] = ftf(x1);
    }
}

// ---------------------------------------------------------------------------
// Flash-style causal attention (R5 structure) with LDSM fragment loads.
// 128 threads (4 warps), 64 queries/CTA, smem P, 2-buffer cp.async, LPT.
// K tiles [key][dim] (LDSM-natural for QK^T B), V tiles [dim][key]
// (LDSM-natural for PV B), P [q][key] (LDSM-natural A).
// ---------------------------------------------------------------------------
#define KS_STRIDE 68
#define VS_STRIDE 68
#define PS_STRIDE 68
#define K_WORDS (64 * KS_STRIDE)
#define V_WORDS (64 * VS_STRIDE)
#define P_WORDS (64 * PS_STRIDE)
#define ATTN_SMEM ((2 * K_WORDS + 2 * V_WORDS + P_WORDS) * 4)   // 87040 B

__device__ __forceinline__ void attn_load_tile(
    uint32_t kbuf, uint32_t vbuf,
    const float* Kg, const float* VgT, int kbase, int tid)
{
    #pragma unroll
    for (int i = 0; i < 8; i++) {
        int f = tid + i * 128;
        int row = f >> 4;
        int c = (f & 15) * 4;
        // K: row = key, c = dim
        cp16(kbuf + (row * KS_STRIDE + c) * 4,
             Kg + (size_t)(kbase + row) * HEAD_D + c);
        // V: row = dim, c = key offset
        cp16(vbuf + (row * VS_STRIDE + c) * 4,
             VgT + (size_t)row * T_SEQ + kbase + c);
    }
}

__global__ __launch_bounds__(128) void attn_kernel()
{
    extern __shared__ float sm[];
    float* Ps = sm + 2 * K_WORDS + 2 * V_WORDS;
    const uint32_t su = (uint32_t)__cvta_generic_to_shared(sm);
    const uint32_t kbu[2] = { su, su + K_WORDS * 4 };
    const uint32_t vbu[2] = { su + 2 * K_WORDS * 4, su + (2 * K_WORDS + V_WORDS) * 4 };
    const uint32_t psu    = su + (2 * K_WORDS + 2 * V_WORDS) * 4;

    const int h    = blockIdx.x;
    const int qt   = gridDim.y - 1 - blockIdx.y;   // LPT
    const int tid  = threadIdx.x;
    const int w    = tid >> 5;
    const int lane = tid & 31;
    const int g    = lane >> 2;
    const int t    = lane & 3;
    const int grp  = h >> 2;
    const int qw0  = qt * 64 + w * 16;

    // ldmatrix lane geometry
    const int lrow = (lane & 7) + ((lane >> 3) & 1) * 8;
    const int lcol = (lane >> 4) * 4;

    const float* Kg  = g_K  + (size_t)grp * T_SEQ * HEAD_D;
    const float* VgT = g_Vt + (size_t)grp * HEAD_D * T_SEQ;

    unsigned qa[8][4];
    {
        const float* Qb = g_Q + ((size_t)h * T_SEQ + qw0) * HEAD_D;
        #pragma unroll
        for (int ks = 0; ks < 8; ks++) {
            qa[ks][0] = __float_as_uint(Qb[(size_t)(g    ) * HEAD_D + ks * 8 + t    ]);
            qa[ks][1] = __float_as_uint(Qb[(size_t)(g + 8) * HEAD_D + ks * 8 + t    ]);
            qa[ks][2] = __float_as_uint(Qb[(size_t)(g    ) * HEAD_D + ks * 8 + t + 4]);
            qa[ks][3] = __float_as_uint(Qb[(size_t)(g + 8) * HEAD_D + ks * 8 + t + 4]);
        }
    }

    float oc[8][4];
    #pragma unroll
    for (int nt = 0; nt < 8; nt++)
        #pragma unroll
        for (int i = 0; i < 4; i++) oc[nt][i] = 0.0f;
    float l0 = 0.0f, l1 = 0.0f;

    attn_load_tile(kbu[0], vbu[0], Kg, VgT, 0, tid);
    cp_commit();

    int buf = 0;
    for (int kt = 0; kt <= qt; kt++) {
        const int kbase = kt * 64;
        cp_wait<0>();
        __syncthreads();
        if (kt < qt) {
            attn_load_tile(kbu[buf ^ 1], vbu[buf ^ 1], Kg, VgT, kbase + 64, tid);
        }
        cp_commit();

        const uint32_t kb = kbu[buf];
        const uint32_t vb = vbu[buf];

        // S = Q @ K^T  — K fragments via LDSM (keys are rows)
        float sc[8][4];
        #pragma unroll
        for (int nt = 0; nt < 8; nt++)
            #pragma unroll
            for (int i = 0; i < 4; i++) sc[nt][i] = 0.0f;

        #pragma unroll
        for (int ks = 0; ks < 8; ks++) {
            #pragma unroll
            for (int p = 0; p < 4; p++) {
                unsigned bf[4];
                ldsm4(bf, kb + ((p * 16 + lrow) * KS_STRIDE + ks * 8 + lcol) * 4);
                mma_tf32(sc[2 * p    ], qa[ks], bf[0], bf[2]);
                mma_tf32(sc[2 * p + 1], qa[ks], bf[1], bf[3]);
            }
        }

        // exp (+causal mask on diagonal), accumulate l, store P (tf32)
        const bool diag = (kt == qt);
        #pragma unroll
        for (int nt = 0; nt < 8; nt++) {
            int k0 = kbase + nt * 8 + 2 * t;
            float p0 = __expf(sc[nt][0]);
            float p1 = __expf(sc[nt][1]);
            float p2 = __expf(sc[nt][2]);
            float p3 = __expf(sc[nt][3]);
            if (diag) {
                int q0 = qw0 + g, q1 = qw0 + g + 8;
                if (k0     > q0) p0 = 0.0f;
                if (k0 + 1 > q0) p1 = 0.0f;
                if (k0     > q1) p2 = 0.0f;
                if (k0 + 1 > q1) p3 = 0.0f;
            }
            l0 += p0 + p1;
            l1 += p2 + p3;
            int c = nt * 8 + 2 * t;
            Ps[(w * 16 + g    ) * PS_STRIDE + c    ] = ftf(p0);
            Ps[(w * 16 + g    ) * PS_STRIDE + c + 1] = ftf(p1);
            Ps[(w * 16 + g + 8) * PS_STRIDE + c    ] = ftf(p2);
            Ps[(w * 16 + g + 8) * PS_STRIDE + c + 1] = ftf(p3);
        }
        __syncwarp();   // Ps slab is warp-private

        // O += P @ V — P A-frags and V_T B-frags via LDSM
        #pragma unroll
        for (int ks = 0; ks < 8; ks++) {
            unsigned pa[4];
            ldsm4(pa, psu + ((w * 16 + lrow) * PS_STRIDE + ks * 8 + lcol) * 4);
            #pragma unroll
            for (int p = 0; p < 4; p++) {
                unsigned bf[4];
                ldsm4(bf, vb + ((p * 16 + lrow) * VS_STRIDE + ks * 8 + lcol) * 4);
                mma_tf32(oc[2 * p    ], pa, bf[0], bf[2]);
                mma_tf32(oc[2 * p + 1], pa, bf[1], bf[3]);
            }
        }
        buf ^= 1;
    }

    l0 += __shfl_xor_sync(0xffffffff, l0, 1);
    l0 += __shfl_xor_sync(0xffffffff, l0, 2);
    l1 += __shfl_xor_sync(0xffffffff, l1, 1);
    l1 += __shfl_xor_sync(0xffffffff, l1, 2);
    float inv0 = 1.0f / l0;
    float inv1 = 1.0f / l1;

    float* Y0 = g_Y + (size_t)(qw0 + g    ) * C_EMB + h * HEAD_D;
    float* Y1 = g_Y + (size_t)(qw0 + g + 8) * C_EMB + h * HEAD_D;
    #pragma unroll
    for (int nt = 0; nt < 8; nt++) {
        int c = nt * 8 + 2 * t;
        *(float2*)(Y0 + c) = make_float2(ftf(oc[nt][0] * inv0), ftf(oc[nt][1] * inv0));
        *(float2*)(Y1 + c) = make_float2(ftf(oc[nt][2] * inv1), ftf(oc[nt][3] * inv1));
    }
}

// ---------------------------------------------------------------------------
extern "C" void kernel_launch(void* const* d_in, const int* in_sizes, int n_in,
                              void* d_out, int out_size)
{
    const float* x      = (const float*)d_in[0];   // [1,2048,1024]
    const float* w_attn = (const float*)d_in[1];   // [1024,1536]
    const float* w_proj = (const float*)d_in[2];   // [1024,1024]
    float* out = (float*)d_out;                    // [1,2048,1024]

    float *xr, *waT, *wpT, *qkv, *Y;
    cudaGetSymbolAddress((void**)&xr,  g_x);
    cudaGetSymbolAddress((void**)&waT, g_waT);
    cudaGetSymbolAddress((void**)&wpT, g_wpT);
    cudaGetSymbolAddress((void**)&qkv, g_qkv);
    cudaGetSymbolAddress((void**)&Y,   g_Y);

    cudaFuncSetAttribute(gemm_tf32,
                         cudaFuncAttributeMaxDynamicSharedMemorySize, GEMM_SMEM);
    cudaFuncSetAttribute(attn_kernel,
                         cudaFuncAttributeMaxDynamicSharedMemorySize, ATTN_SMEM);

    // 0) pre-round x; transpose+round weights; rope table
    {
        int n1 = T_SEQ * C_EMB;
        round_tf32<<<(n1 / 4 + 255) / 256, 256>>>(x, xr, n1);
        dim3 blk(32, 8);
        transpose_round<<<dim3(QKV_DIM / 32, C_EMB / 32), blk>>>(w_attn, waT,
                                                                 C_EMB, QKV_DIM);
        transpose_round<<<dim3(C_EMB / 32, C_EMB / 32), blk>>>(w_proj, wpT,
                                                               C_EMB, C_EMB);
        build_rope<<<(T_SEQ * 32 + 255) / 256, 256>>>();
    }
    // 1) QKV = x @ w_attn
    {
        dim3 grid(QKV_DIM / 128, T_SEQ / 64);
        gemm_tf32<<<grid, 256, GEMM_SMEM>>>(xr, waT, qkv, T_SEQ, QKV_DIM, C_EMB);
    }
    // 2) RoPE + split (V transposed)
    {
        int total = T_SEQ * (QKV_DIM / 2);
        rope_split<<<(total + 255) / 256, 256>>>(qkv);
    }
    // 3) attention
    {
        dim3 grid(N_HEAD, T_SEQ / 64);
        attn_kernel<<<grid, 128, ATTN_SMEM>>>();
    }
    // 4) out = Y @ w_proj
    {
        dim3 grid(C_EMB / 128, T_SEQ / 64);
        gemm_tf32<<<grid, 256, GEMM_SMEM>>>(Y, wpT, out, T_SEQ, C_EMB, C_EMB);
    }
}